// round 5
// baseline (speedup 1.0000x reference)
#include <cuda_runtime.h>
#include <cuda_bf16.h>
#include <math.h>
#include <stdint.h>

// Problem shape (fixed by setup_inputs)
#define MROWS 32768          // B*L
#define BDIM  8
#define LSEQ  4096
#define HD    1024
#define NL    4
#define K3    3072           // 3 * HD (bf16-split K)
#define NCHK  48             // K3 / 64

// GEMM tiling
#define BM 128
#define BN 256
#define BK 64
#define NSTAGE 3
#define ROWB 144                          // (64+8) bf16 = 144 bytes per row
#define A_STG_BYTES (BM * ROWB)           // 18432
#define B_STG_BYTES (BN * ROWB)           // 36864
#define STG_BYTES (A_STG_BYTES + B_STG_BYTES)   // 55296
#define GEMM_SMEM (NSTAGE * STG_BYTES)          // 165888

// ---------------------------------------------------------------------------
// Scratch (device globals: allocation-free)
// ---------------------------------------------------------------------------
__device__ float g_bufA[(size_t)MROWS * HD];
__device__ float g_bufB[(size_t)MROWS * HD];
__device__ __align__(256) __nv_bfloat16 g_A2[(size_t)MROWS * K3];   // split A
__device__ __align__(256) __nv_bfloat16 g_Wt1[(size_t)HD * K3];     // split lt_w^T
__device__ __align__(256) __nv_bfloat16 g_Wt2[(size_t)HD * K3];     // split ft_w^T

// ---------------------------------------------------------------------------
// PTX helpers (sm_80-class features only: cp.async, ldmatrix, mma.sync)
// ---------------------------------------------------------------------------
__device__ __forceinline__ uint32_t smem_to_u32(const void* p) {
    uint32_t a;
    asm("{ .reg .u64 t; cvta.to.shared.u64 t, %1; cvt.u32.u64 %0, t; }" : "=r"(a) : "l"(p));
    return a;
}
__device__ __forceinline__ void cp_async16(uint32_t dst, const void* src) {
    asm volatile("cp.async.cg.shared.global [%0], [%1], 16;\n" :: "r"(dst), "l"(src) : "memory");
}
#define CP_COMMIT() asm volatile("cp.async.commit_group;" ::: "memory")
#define CP_WAIT1()  asm volatile("cp.async.wait_group 1;" ::: "memory")

__device__ __forceinline__ void ldsm_x4(uint32_t (&r)[4], uint32_t addr) {
    asm volatile("ldmatrix.sync.aligned.m8n8.x4.shared.b16 {%0,%1,%2,%3}, [%4];"
        : "=r"(r[0]), "=r"(r[1]), "=r"(r[2]), "=r"(r[3]) : "r"(addr));
}
__device__ __forceinline__ void mma16816(float (&c)[4],
                                         const uint32_t (&a)[4],
                                         uint32_t b0, uint32_t b1) {
    asm volatile(
        "mma.sync.aligned.m16n8k16.row.col.f32.bf16.bf16.f32 "
        "{%0,%1,%2,%3}, {%4,%5,%6,%7}, {%8,%9}, {%0,%1,%2,%3};"
        : "+f"(c[0]), "+f"(c[1]), "+f"(c[2]), "+f"(c[3])
        : "r"(a[0]), "r"(a[1]), "r"(a[2]), "r"(a[3]), "r"(b0), "r"(b1));
}

// split a float into (hi, hi, lo) bf16 triple at dst
__device__ __forceinline__ void store_split3(__nv_bfloat16* dst, float v) {
    const __nv_bfloat16 hi = __float2bfloat16_rn(v);
    const __nv_bfloat16 lo = __float2bfloat16_rn(v - __bfloat162float(hi));
    dst[0] = hi; dst[1] = hi; dst[2] = lo;
}

// ---------------------------------------------------------------------------
// Split conversion: A[M,HD] fp32 -> A2[M,3*HD] bf16 pattern (hi, hi, lo)
// ---------------------------------------------------------------------------
__global__ __launch_bounds__(256) void convA_kernel(
    const float* __restrict__ A, __nv_bfloat16* __restrict__ A2)
{
    const size_t i = (size_t)blockIdx.x * 256 + threadIdx.x;
    const float4 v = *(const float4*)(A + i * 4);
    float f[4] = {v.x, v.y, v.z, v.w};
    __nv_bfloat16 h[12];
    #pragma unroll
    for (int j = 0; j < 4; ++j) {
        __nv_bfloat16 hi = __float2bfloat16_rn(f[j]);
        __nv_bfloat16 lo = __float2bfloat16_rn(f[j] - __bfloat162float(hi));
        h[3 * j + 0] = hi; h[3 * j + 1] = hi; h[3 * j + 2] = lo;
    }
    unsigned long long* dst = (unsigned long long*)(A2 + i * 12);
    const unsigned long long* src = (const unsigned long long*)h;
    dst[0] = src[0]; dst[1] = src[1]; dst[2] = src[2];
}

// W[HD,HD] fp32 -> Wt[n, 3k] bf16 pattern (hi, lo, hi), transposed
__global__ __launch_bounds__(256) void convW_kernel(
    const float* __restrict__ W, __nv_bfloat16* __restrict__ Wt)
{
    const int idx = blockIdx.x * 256 + threadIdx.x;   // HD*HD threads
    const int n = idx & (HD - 1);
    const int k = idx >> 10;
    const float w = W[(size_t)k * HD + n];
    __nv_bfloat16 hi = __float2bfloat16_rn(w);
    __nv_bfloat16 lo = __float2bfloat16_rn(w - __bfloat162float(hi));
    const size_t o = (size_t)n * K3 + 3 * k;
    Wt[o] = hi; Wt[o + 1] = lo; Wt[o + 2] = hi;
}

// ---------------------------------------------------------------------------
// mma.sync GEMM: C[M,HD] = A2[M,K3] x Wt[HD,K3]^T + bias
// CTA 128x256, 16 warps (4x4), warp tile 32x64, BK=64, 3-stage cp.async.
// ---------------------------------------------------------------------------
__global__ __launch_bounds__(512, 1) void gemm_mma_kernel(
    const __nv_bfloat16* __restrict__ A2,
    const __nv_bfloat16* __restrict__ Wt,
    const float* __restrict__ bias,
    float* __restrict__ C)
{
    extern __shared__ char smem_raw[];
    const uint32_t sbase = smem_to_u32(smem_raw);

    const int tid = threadIdx.x;
    const int wid = tid >> 5;
    const int lane = tid & 31;
    const int m0 = blockIdx.y * BM;
    const int n0 = blockIdx.x * BN;

    const int wm = (wid >> 2) * 32;      // warp M offset (0..96)
    const int wn = (wid & 3) * 64;       // warp N offset (0..192)

    // ---- global load addressing: per thread 2 A-chunks + 4 B-chunks (16B) ----
    const int lr = tid >> 3;             // 0..63
    const int lc = tid & 7;              // 16B chunk within 128B row
    const __nv_bfloat16* gA0 = A2 + (size_t)(m0 + lr) * K3 + lc * 8;
    const __nv_bfloat16* gA1 = gA0 + (size_t)64 * K3;
    const __nv_bfloat16* gB0 = Wt + (size_t)(n0 + lr) * K3 + lc * 8;
    const __nv_bfloat16* gB1 = gB0 + (size_t)64 * K3;
    const __nv_bfloat16* gB2 = gB0 + (size_t)128 * K3;
    const __nv_bfloat16* gB3 = gB0 + (size_t)192 * K3;

    const uint32_t sA_off = lr * ROWB + lc * 16;
    const uint32_t sB_off = A_STG_BYTES + lr * ROWB + lc * 16;
    const uint32_t RSTEP = 64 * ROWB;    // 64 rows

    // ---- ldmatrix addressing (per lane) ----
    const int lrow = lane & 15;
    const int lkof = (lane >> 4) * 16;   // byte offset of 8-elem k-half
    const uint32_t aAddrBase = sbase + (wm + lrow) * ROWB + lkof;
    const uint32_t bAddrBase = sbase + A_STG_BYTES + (wn + lrow) * ROWB + lkof;

    float acc[2][8][4];
    #pragma unroll
    for (int i = 0; i < 2; ++i)
        #pragma unroll
        for (int j = 0; j < 8; ++j)
            #pragma unroll
            for (int q = 0; q < 4; ++q) acc[i][j][q] = 0.0f;

    // ---- pipeline prologue: chunks 0,1 into stages 0,1 ----
    #pragma unroll
    for (int p = 0; p < 2; ++p) {
        const uint32_t sb = sbase + p * STG_BYTES;
        const size_t go = (size_t)p * BK;
        cp_async16(sb + sA_off,             gA0 + go);
        cp_async16(sb + sA_off + RSTEP,     gA1 + go);
        cp_async16(sb + sB_off,             gB0 + go);
        cp_async16(sb + sB_off + RSTEP,     gB1 + go);
        cp_async16(sb + sB_off + 2 * RSTEP, gB2 + go);
        cp_async16(sb + sB_off + 3 * RSTEP, gB3 + go);
        CP_COMMIT();
    }

    int s_c = 0;   // stage of chunk kc
    int s_q = 2;   // stage of chunk kc+2
    #pragma unroll 1
    for (int kc = 0; kc < NCHK; ++kc) {
        CP_WAIT1();
        __syncthreads();

        // issue loads for chunk kc+2 first (overlap with compute below);
        // stage s_q held chunk kc-1, finished by all warps before the barrier
        const int q = kc + 2;
        if (q < NCHK) {
            const uint32_t sb = sbase + s_q * STG_BYTES;
            const size_t go = (size_t)q * BK;
            cp_async16(sb + sA_off,             gA0 + go);
            cp_async16(sb + sA_off + RSTEP,     gA1 + go);
            cp_async16(sb + sB_off,             gB0 + go);
            cp_async16(sb + sB_off + RSTEP,     gB1 + go);
            cp_async16(sb + sB_off + 2 * RSTEP, gB2 + go);
            cp_async16(sb + sB_off + 3 * RSTEP, gB3 + go);
        }
        CP_COMMIT();

        const uint32_t stg = s_c * STG_BYTES;
        #pragma unroll
        for (int ks = 0; ks < 4; ++ks) {
            uint32_t a[2][4], b[4][4];
            const uint32_t kb = stg + ks * 32;            // 16 bf16 = 32 bytes
            #pragma unroll
            for (int i = 0; i < 2; ++i)
                ldsm_x4(a[i], aAddrBase + kb + i * (16 * ROWB));
            #pragma unroll
            for (int j = 0; j < 4; ++j)
                ldsm_x4(b[j], bAddrBase + kb + j * (16 * ROWB));
            #pragma unroll
            for (int i = 0; i < 2; ++i) {
                #pragma unroll
                for (int j = 0; j < 4; ++j) {
                    mma16816(acc[i][2 * j + 0], a[i], b[j][0], b[j][2]);
                    mma16816(acc[i][2 * j + 1], a[i], b[j][1], b[j][3]);
                }
            }
        }

        if (++s_c == NSTAGE) s_c = 0;
        if (++s_q == NSTAGE) s_q = 0;
    }

    // ---- epilogue: bias add + store ----
    const int g = lane >> 2;             // 0..7
    const int t = lane & 3;              // 0..3
    #pragma unroll
    for (int i = 0; i < 2; ++i) {
        const int row = m0 + wm + i * 16 + g;
        #pragma unroll
        for (int j = 0; j < 8; ++j) {
            const int col = n0 + wn + j * 8 + t * 2;
            const float b0 = bias[col], b1 = bias[col + 1];
            float2 v0 = make_float2(acc[i][j][0] + b0, acc[i][j][1] + b1);
            float2 v1 = make_float2(acc[i][j][2] + b0, acc[i][j][3] + b1);
            *(float2*)(C + (size_t)row * HD + col) = v0;
            *(float2*)(C + (size_t)(row + 8) * HD + col) = v1;
        }
    }
}

// ---------------------------------------------------------------------------
// Block reduction helper (256 threads)
// ---------------------------------------------------------------------------
__device__ __forceinline__ float blk_reduce(float v, float* sbuf)
{
    #pragma unroll
    for (int o = 16; o > 0; o >>= 1) v += __shfl_down_sync(0xffffffffu, v, o);
    const int lane = threadIdx.x & 31;
    const int w = threadIdx.x >> 5;
    if (lane == 0) sbuf[w] = v;
    __syncthreads();
    if (threadIdx.x < 32) {
        float x = (threadIdx.x < 8) ? sbuf[threadIdx.x] : 0.0f;
        #pragma unroll
        for (int o = 4; o > 0; o >>= 1) x += __shfl_down_sync(0xffffffffu, x, o);
        if (threadIdx.x == 0) sbuf[0] = x;
    }
    __syncthreads();
    float r = sbuf[0];
    __syncthreads();
    return r;
}

// ---------------------------------------------------------------------------
// LN1 + hierarchical fusion (one block per row)
// ---------------------------------------------------------------------------
__global__ __launch_bounds__(256) void ln1_fusion_kernel(
    const float* __restrict__ Y, const float* __restrict__ masks,
    const float* __restrict__ emb,
    const float* __restrict__ g, const float* __restrict__ bvec,
    float* __restrict__ Fout)
{
    __shared__ float s_emb[NL * HD];
    __shared__ float sbuf[8];

    const int row = blockIdx.x;
    const int c = threadIdx.x * 4;

    for (int i = threadIdx.x; i < NL * HD; i += 256) s_emb[i] = emb[i];
    __syncthreads();

    const float4 y = *(const float4*)(Y + (size_t)row * HD + c);
    float s  = y.x + y.y + y.z + y.w;
    float sq = y.x * y.x + y.y * y.y + y.z * y.z + y.w * y.w;
    const float sum   = blk_reduce(s, sbuf);
    const float sumsq = blk_reduce(sq, sbuf);
    const float mu   = sum * (1.0f / HD);
    const float var  = sumsq * (1.0f / HD) - mu * mu;
    const float rstd = rsqrtf(var + 1e-5f);

    const float4 gv = *(const float4*)(g + c);
    const float4 bv = *(const float4*)(bvec + c);
    const float t0 = (y.x - mu) * rstd * gv.x + bv.x;
    const float t1 = (y.y - mu) * rstd * gv.y + bv.y;
    const float t2 = (y.z - mu) * rstd * gv.z + bv.z;
    const float t3 = (y.w - mu) * rstd * gv.w + bv.w;

    float sc[NL];
    #pragma unroll
    for (int n = 0; n < NL; ++n) {
        const float* e = s_emb + n * HD + c;
        float p = t0 * e[0] + t1 * e[1] + t2 * e[2] + t3 * e[3];
        sc[n] = blk_reduce(p, sbuf);
    }

    const float4 mk = *(const float4*)(masks + (size_t)row * 4);
    float wn0 = (mk.x > 0.5f) ? expf(sc[0]) : 0.0f;
    float wn1 = (mk.y > 0.5f) ? expf(sc[1]) : 0.0f;
    float wn2 = (mk.z > 0.5f) ? expf(sc[2]) : 0.0f;
    float wn3 = (mk.w > 0.5f) ? expf(sc[3]) : 0.0f;
    const float tot = wn0 + wn1 + wn2 + wn3;
    const float inv = (tot > 1e-8f) ? (1.0f / tot) : 1.0f;

    const float* e0 = s_emb + 0 * HD + c;
    const float* e1 = s_emb + 1 * HD + c;
    const float* e2 = s_emb + 2 * HD + c;
    const float* e3 = s_emb + 3 * HD + c;
    const float f0 = (wn0 * e0[0] + wn1 * e1[0] + wn2 * e2[0] + wn3 * e3[0]) * inv;
    const float f1 = (wn0 * e0[1] + wn1 * e1[1] + wn2 * e2[1] + wn3 * e3[1]) * inv;
    const float f2 = (wn0 * e0[2] + wn1 * e1[2] + wn2 * e2[2] + wn3 * e3[2]) * inv;
    const float f3 = (wn0 * e0[3] + wn1 * e1[3] + wn2 * e2[3] + wn3 * e3[3]) * inv;

    const float gd = f0 * t0 + f1 * t1 + f2 * t2 + f3 * t3;
    const float gsum = blk_reduce(gd, sbuf);
    const float gate = 1.0f / (1.0f + expf(-gsum * (1.0f / HD)));
    const float og = 1.0f - gate;

    float4 o;
    o.x = gate * f0 + og * t0;
    o.y = gate * f1 + og * t1;
    o.z = gate * f2 + og * t2;
    o.w = gate * f3 + og * t3;
    *(float4*)(Fout + (size_t)row * HD + c) = o;
}

// ---------------------------------------------------------------------------
// Multi-scale windowed means along L (scales 1,3,7,15), fused bf16-split out
// Writes A2[m, 3k] (hi,hi,lo) directly for GEMM2.
// ---------------------------------------------------------------------------
__global__ __launch_bounds__(256) void multiscale_kernel(
    const float* __restrict__ F, __nv_bfloat16* __restrict__ A2)
{
    const int L = LSEQ, H = HD;
    const int SL = 128;

    const int gtid = blockIdx.x * 256 + threadIdx.x;
    const int h = gtid & (H - 1);
    const int rest = gtid >> 10;
    const int b = rest & 7;
    const int strip = rest >> 3;
    const int s0 = strip * SL;

    const float* base = F + (size_t)b * L * H + h;
    __nv_bfloat16* oA = A2 + (size_t)b * L * K3 + 3 * h;

    const float SW3  = (float)(1.0 / (1.0 + 1.0986122886681098));
    const float SW7  = (float)(1.0 / (1.0 + 1.9459101090932196));
    const float SW15 = (float)(1.0 / (1.0 + 2.7080502011022101));

    if (strip > 0 && strip < 31) {
        float ring[16];
        #pragma unroll
        for (int j = -8; j <= 6; ++j)
            ring[j & 15] = base[(size_t)(s0 + j) * H];

        float s3 = 0.f, s7 = 0.f, s15 = 0.f;
        #pragma unroll
        for (int j = -8; j <= 6; ++j) {
            const float v = ring[j & 15];
            const int d = j + 1;
            if (d >= -7 && d <= 7) s15 += v;
            if (d >= -3 && d <= 3) s7  += v;
            if (d >= -1 && d <= 1) s3  += v;
        }

        const float w3 = SW3 * (1.0f / 3.0f);
        const float w7 = SW7 * (1.0f / 7.0f);
        const float w15 = SW15 * (1.0f / 15.0f);

        #pragma unroll 1
        for (int cch = 0; cch < SL; cch += 16) {
            #pragma unroll
            for (int i = 0; i < 16; ++i) {
                const int l = s0 + cch + i;
                const float nv = base[(size_t)(l + 7) * H];
                ring[(i + 7) & 15] = nv;
                s3  += ring[(i + 1) & 15] - ring[(i - 2) & 15];
                s7  += ring[(i + 3) & 15] - ring[(i - 4) & 15];
                s15 += nv               - ring[(i - 8) & 15];
                const float s1 = ring[i & 15];
                store_split3(oA + (size_t)l * K3, s1 + s3 * w3 + s7 * w7 + s15 * w15);
            }
        }
    } else {
        for (int l = s0; l < s0 + SL; ++l) {
            float s3 = 0.f, s7 = 0.f, s15 = 0.f;
            #pragma unroll
            for (int j = -7; j <= 7; ++j) {
                const int p = l + j;
                const float v = (p >= 0 && p < L) ? base[(size_t)p * H] : 0.0f;
                s15 += v;
                if (j >= -3 && j <= 3) s7 += v;
                if (j >= -1 && j <= 1) s3 += v;
            }
            const float s1 = base[(size_t)l * H];
            const int cnt3  = min(l + 2, L) - max(l - 1, 0);
            const int cnt7  = min(l + 4, L) - max(l - 3, 0);
            const int cnt15 = min(l + 8, L) - max(l - 7, 0);
            const float outv = s1
                + SW3  * s3  / (float)cnt3
                + SW7  * s7  / (float)cnt7
                + SW15 * s15 / (float)cnt15;
            store_split3(oA + (size_t)l * K3, outv);
        }
    }
}

// ---------------------------------------------------------------------------
// LN2 + residual
// ---------------------------------------------------------------------------
__global__ __launch_bounds__(256) void ln2_res_kernel(
    const float* __restrict__ Y, const float* __restrict__ X,
    const float* __restrict__ g, const float* __restrict__ bvec,
    float* __restrict__ out)
{
    __shared__ float sbuf[8];
    const int row = blockIdx.x;
    const int c = threadIdx.x * 4;

    const float4 y = *(const float4*)(Y + (size_t)row * HD + c);
    float s  = y.x + y.y + y.z + y.w;
    float sq = y.x * y.x + y.y * y.y + y.z * y.z + y.w * y.w;
    const float sum   = blk_reduce(s, sbuf);
    const float sumsq = blk_reduce(sq, sbuf);
    const float mu   = sum * (1.0f / HD);
    const float var  = sumsq * (1.0f / HD) - mu * mu;
    const float rstd = rsqrtf(var + 1e-5f);

    const float4 gv = *(const float4*)(g + c);
    const float4 bv = *(const float4*)(bvec + c);
    const float4 xv = *(const float4*)(X + (size_t)row * HD + c);

    float4 o;
    o.x = (y.x - mu) * rstd * gv.x + bv.x + xv.x;
    o.y = (y.y - mu) * rstd * gv.y + bv.y + xv.y;
    o.z = (y.z - mu) * rstd * gv.z + bv.z + xv.z;
    o.w = (y.w - mu) * rstd * gv.w + bv.w + xv.w;
    *(float4*)(out + (size_t)row * HD + c) = o;
}

// ---------------------------------------------------------------------------
// Launcher
// ---------------------------------------------------------------------------
extern "C" void kernel_launch(void* const* d_in, const int* in_sizes, int n_in,
                              void* d_out, int out_size)
{
    const float* X   = (const float*)d_in[0];
    const float* msk = (const float*)d_in[1];
    const float* emb = (const float*)d_in[2];
    const float* ltw = (const float*)d_in[3];
    const float* ltb = (const float*)d_in[4];
    const float* g1  = (const float*)d_in[5];
    const float* b1  = (const float*)d_in[6];
    const float* ftw = (const float*)d_in[7];
    const float* ftb = (const float*)d_in[8];
    const float* g2  = (const float*)d_in[9];
    const float* b2  = (const float*)d_in[10];
    float* out = (float*)d_out;

    float *bufA, *bufB;
    __nv_bfloat16 *A2, *Wt1, *Wt2;
    cudaGetSymbolAddress((void**)&bufA, g_bufA);
    cudaGetSymbolAddress((void**)&bufB, g_bufB);
    cudaGetSymbolAddress((void**)&A2,  g_A2);
    cudaGetSymbolAddress((void**)&Wt1, g_Wt1);
    cudaGetSymbolAddress((void**)&Wt2, g_Wt2);

    cudaFuncSetAttribute((const void*)gemm_mma_kernel,
                         cudaFuncAttributeMaxDynamicSharedMemorySize, GEMM_SMEM);

    const dim3 ggrid(HD / BN, MROWS / BM);   // (4, 256)

    // weight splits (every call; deterministic)
    convW_kernel<<<(HD * HD) / 256, 256>>>(ltw, Wt1);
    convW_kernel<<<(HD * HD) / 256, 256>>>(ftw, Wt2);

    // 1) Y1 = X @ lt_w + lt_b
    convA_kernel<<<(MROWS * HD / 4) / 256, 256>>>(X, A2);
    gemm_mma_kernel<<<ggrid, 512, GEMM_SMEM>>>(A2, Wt1, ltb, bufA);
    // 2) F = fusion(LN1(Y1))
    ln1_fusion_kernel<<<MROWS, 256>>>(bufA, msk, emb, g1, b1, bufB);
    // 3) agg = multiscale(F) fused with bf16 split -> A2
    multiscale_kernel<<<(BDIM * HD * 32) / 256, 256>>>(bufB, A2);
    // 4) Y2 = agg @ ft_w + ft_b
    gemm_mma_kernel<<<ggrid, 512, GEMM_SMEM>>>(A2, Wt2, ftb, bufA);
    // 5) out = LN2(Y2) + X
    ln2_res_kernel<<<MROWS, 256>>>(bufA, X, g2, b2, out);
}

// round 6
// speedup vs baseline: 1.9792x; 1.9792x over previous
#include <cuda_runtime.h>
#include <cuda_fp16.h>
#include <math.h>
#include <stdint.h>

// Problem shape (fixed by setup_inputs)
#define MROWS 32768          // B*L
#define BDIM  8
#define LSEQ  4096
#define HD    1024
#define NL    4
#define NCHK  32             // HD / BK

// GEMM tiling: CTA 128x256, 8 warps (2x4), warp tile 64x64, BK=32
#define BM 128
#define BN 256
#define BK 32
#define NSTAGE 5
#define ROWB 80                           // (32+8) fp16 = 80 bytes per row
#define A_STG (BM * ROWB)                 // 10240
#define B_STG (BN * ROWB)                 // 20480
#define STG   (A_STG + B_STG)             // 30720
#define GEMM_SMEM (NSTAGE * STG)          // 153600

// ---------------------------------------------------------------------------
// Scratch (device globals: allocation-free)
// ---------------------------------------------------------------------------
__device__ float g_bufA[(size_t)MROWS * HD];
__device__ float g_bufB[(size_t)MROWS * HD];
__device__ __align__(256) __half g_A2[(size_t)MROWS * HD];    // fp16 A
__device__ __align__(256) __half g_Wt1[(size_t)HD * HD];      // lt_w^T fp16
__device__ __align__(256) __half g_Wt2[(size_t)HD * HD];      // ft_w^T fp16

// ---------------------------------------------------------------------------
// PTX helpers (sm_80-class features only: cp.async, ldmatrix, mma.sync)
// ---------------------------------------------------------------------------
__device__ __forceinline__ uint32_t smem_to_u32(const void* p) {
    uint32_t a;
    asm("{ .reg .u64 t; cvta.to.shared.u64 t, %1; cvt.u32.u64 %0, t; }" : "=r"(a) : "l"(p));
    return a;
}
__device__ __forceinline__ void cp_async16(uint32_t dst, const void* src) {
    asm volatile("cp.async.cg.shared.global [%0], [%1], 16;\n" :: "r"(dst), "l"(src) : "memory");
}
#define CP_COMMIT() asm volatile("cp.async.commit_group;" ::: "memory")
#define CP_WAIT3()  asm volatile("cp.async.wait_group 3;" ::: "memory")

__device__ __forceinline__ void ldsm_x4(uint32_t (&r)[4], uint32_t addr) {
    asm volatile("ldmatrix.sync.aligned.m8n8.x4.shared.b16 {%0,%1,%2,%3}, [%4];"
        : "=r"(r[0]), "=r"(r[1]), "=r"(r[2]), "=r"(r[3]) : "r"(addr));
}
__device__ __forceinline__ void mma16816(float (&c)[4],
                                         const uint32_t (&a)[4],
                                         uint32_t b0, uint32_t b1) {
    asm volatile(
        "mma.sync.aligned.m16n8k16.row.col.f32.f16.f16.f32 "
        "{%0,%1,%2,%3}, {%4,%5,%6,%7}, {%8,%9}, {%0,%1,%2,%3};"
        : "+f"(c[0]), "+f"(c[1]), "+f"(c[2]), "+f"(c[3])
        : "r"(a[0]), "r"(a[1]), "r"(a[2]), "r"(a[3]), "r"(b0), "r"(b1));
}

// ---------------------------------------------------------------------------
// fp32 -> fp16 conversion of A [M, HD]
// ---------------------------------------------------------------------------
__global__ __launch_bounds__(256) void convA_kernel(
    const float* __restrict__ A, __half* __restrict__ A2)
{
    const size_t i = (size_t)blockIdx.x * 256 + threadIdx.x;
    const float4 v = *(const float4*)(A + i * 4);
    __half h[4];
    h[0] = __float2half_rn(v.x); h[1] = __float2half_rn(v.y);
    h[2] = __float2half_rn(v.z); h[3] = __float2half_rn(v.w);
    ((unsigned long long*)A2)[i] = *(const unsigned long long*)h;
}

// W[HD,HD] fp32 -> Wt[n][k] fp16 (transposed)
__global__ __launch_bounds__(256) void convW_kernel(
    const float* __restrict__ W, __half* __restrict__ Wt)
{
    const int idx = blockIdx.x * 256 + threadIdx.x;   // HD*HD threads
    const int n = idx & (HD - 1);
    const int k = idx >> 10;
    Wt[(size_t)n * HD + k] = __float2half_rn(W[(size_t)k * HD + n]);
}

// ---------------------------------------------------------------------------
// mma.sync GEMM: C[M,HD] = A2[M,HD](f16) x Wt[HD,HD](f16,K-major)^T + bias
// CTA 128x256, 8 warps (2x4), warp tile 64x64, BK=32, 5-stage cp.async.
// ---------------------------------------------------------------------------
__global__ __launch_bounds__(256, 1) void gemm_mma_kernel(
    const __half* __restrict__ A2,
    const __half* __restrict__ Wt,
    const float* __restrict__ bias,
    float* __restrict__ C)
{
    extern __shared__ char smem_raw[];
    const uint32_t sbase = smem_to_u32(smem_raw);

    const int tid = threadIdx.x;
    const int wid = tid >> 5;
    const int lane = tid & 31;
    const int m0 = blockIdx.y * BM;
    const int n0 = blockIdx.x * BN;

    const int wm = (wid >> 2) * 64;      // warp M offset (0/64)
    const int wn = (wid & 3) * 64;       // warp N offset (0..192)

    // ---- global load addressing: per thread 2 A-chunks + 4 B-chunks (16B) ----
    const int lr = tid >> 2;             // 0..63
    const int lc = tid & 3;              // 16B chunk within 64B row
    const __half* gA0 = A2 + (size_t)(m0 + lr) * HD + lc * 8;
    const __half* gA1 = gA0 + (size_t)64 * HD;
    const __half* gB0 = Wt + (size_t)(n0 + lr) * HD + lc * 8;
    const __half* gB1 = gB0 + (size_t)64 * HD;
    const __half* gB2 = gB0 + (size_t)128 * HD;
    const __half* gB3 = gB0 + (size_t)192 * HD;

    const uint32_t sA_off = lr * ROWB + lc * 16;
    const uint32_t sB_off = A_STG + lr * ROWB + lc * 16;
    const uint32_t RSTEP = 64 * ROWB;    // 64 rows = 5120 B

    // ---- ldmatrix addressing (per lane) ----
    const int lrow = lane & 15;
    const int lkof = (lane >> 4) * 16;
    const uint32_t aAddrBase = sbase + (wm + lrow) * ROWB + lkof;
    const uint32_t bAddrBase = sbase + A_STG + (wn + lrow) * ROWB + lkof;

    float acc[4][8][4];
    #pragma unroll
    for (int i = 0; i < 4; ++i)
        #pragma unroll
        for (int j = 0; j < 8; ++j)
            #pragma unroll
            for (int q = 0; q < 4; ++q) acc[i][j][q] = 0.0f;

    // ---- pipeline prologue: chunks 0..3 into stages 0..3 ----
    #pragma unroll
    for (int p = 0; p < 4; ++p) {
        const uint32_t sb = sbase + p * STG;
        const size_t go = (size_t)p * BK;
        cp_async16(sb + sA_off,             gA0 + go);
        cp_async16(sb + sA_off + RSTEP,     gA1 + go);
        cp_async16(sb + sB_off,             gB0 + go);
        cp_async16(sb + sB_off + RSTEP,     gB1 + go);
        cp_async16(sb + sB_off + 2 * RSTEP, gB2 + go);
        cp_async16(sb + sB_off + 3 * RSTEP, gB3 + go);
        CP_COMMIT();
    }

    int s_c = 0;   // stage of chunk kc
    int s_q = 4;   // stage of chunk kc+4
    #pragma unroll 1
    for (int kc = 0; kc < NCHK; ++kc) {
        CP_WAIT3();               // chunk kc landed (<=3 younger outstanding)
        __syncthreads();

        // issue loads for chunk kc+4 (stage held chunk kc-1, done by all warps)
        const int q = kc + 4;
        if (q < NCHK) {
            const uint32_t sb = sbase + s_q * STG;
            const size_t go = (size_t)q * BK;
            cp_async16(sb + sA_off,             gA0 + go);
            cp_async16(sb + sA_off + RSTEP,     gA1 + go);
            cp_async16(sb + sB_off,             gB0 + go);
            cp_async16(sb + sB_off + RSTEP,     gB1 + go);
            cp_async16(sb + sB_off + 2 * RSTEP, gB2 + go);
            cp_async16(sb + sB_off + 3 * RSTEP, gB3 + go);
        }
        CP_COMMIT();

        const uint32_t stg = s_c * STG;
        // load BOTH ks-halves' fragments up front, then back-to-back MMA
        uint32_t a0[4][4], b0[4][4], a1[4][4], b1[4][4];
        #pragma unroll
        for (int i = 0; i < 4; ++i)
            ldsm_x4(a0[i], aAddrBase + stg + i * (16 * ROWB));
        #pragma unroll
        for (int j = 0; j < 4; ++j)
            ldsm_x4(b0[j], bAddrBase + stg + j * (16 * ROWB));
        #pragma unroll
        for (int i = 0; i < 4; ++i)
            ldsm_x4(a1[i], aAddrBase + stg + 32 + i * (16 * ROWB));
        #pragma unroll
        for (int j = 0; j < 4; ++j)
            ldsm_x4(b1[j], bAddrBase + stg + 32 + j * (16 * ROWB));

        #pragma unroll
        for (int i = 0; i < 4; ++i) {
            #pragma unroll
            for (int j = 0; j < 4; ++j) {
                mma16816(acc[i][2 * j + 0], a0[i], b0[j][0], b0[j][2]);
                mma16816(acc[i][2 * j + 1], a0[i], b0[j][1], b0[j][3]);
            }
        }
        #pragma unroll
        for (int i = 0; i < 4; ++i) {
            #pragma unroll
            for (int j = 0; j < 4; ++j) {
                mma16816(acc[i][2 * j + 0], a1[i], b1[j][0], b1[j][2]);
                mma16816(acc[i][2 * j + 1], a1[i], b1[j][1], b1[j][3]);
            }
        }

        if (++s_c == NSTAGE) s_c = 0;
        if (++s_q == NSTAGE) s_q = 0;
    }

    // ---- epilogue: bias add + store ----
    const int g = lane >> 2;             // 0..7
    const int t = lane & 3;              // 0..3
    #pragma unroll
    for (int i = 0; i < 4; ++i) {
        const int row = m0 + wm + i * 16 + g;
        #pragma unroll
        for (int j = 0; j < 8; ++j) {
            const int col = n0 + wn + j * 8 + t * 2;
            const float b0 = bias[col], b1 = bias[col + 1];
            float2 v0 = make_float2(acc[i][j][0] + b0, acc[i][j][1] + b1);
            float2 v1 = make_float2(acc[i][j][2] + b0, acc[i][j][3] + b1);
            *(float2*)(C + (size_t)row * HD + col) = v0;
            *(float2*)(C + (size_t)(row + 8) * HD + col) = v1;
        }
    }
}

// ---------------------------------------------------------------------------
// Block reduction helper (256 threads)
// ---------------------------------------------------------------------------
__device__ __forceinline__ float blk_reduce(float v, float* sbuf)
{
    #pragma unroll
    for (int o = 16; o > 0; o >>= 1) v += __shfl_down_sync(0xffffffffu, v, o);
    const int lane = threadIdx.x & 31;
    const int w = threadIdx.x >> 5;
    if (lane == 0) sbuf[w] = v;
    __syncthreads();
    if (threadIdx.x < 32) {
        float x = (threadIdx.x < 8) ? sbuf[threadIdx.x] : 0.0f;
        #pragma unroll
        for (int o = 4; o > 0; o >>= 1) x += __shfl_down_sync(0xffffffffu, x, o);
        if (threadIdx.x == 0) sbuf[0] = x;
    }
    __syncthreads();
    float r = sbuf[0];
    __syncthreads();
    return r;
}

// ---------------------------------------------------------------------------
// LN1 + hierarchical fusion (one block per row)
// ---------------------------------------------------------------------------
__global__ __launch_bounds__(256) void ln1_fusion_kernel(
    const float* __restrict__ Y, const float* __restrict__ masks,
    const float* __restrict__ emb,
    const float* __restrict__ g, const float* __restrict__ bvec,
    float* __restrict__ Fout)
{
    __shared__ float s_emb[NL * HD];
    __shared__ float sbuf[8];

    const int row = blockIdx.x;
    const int c = threadIdx.x * 4;

    for (int i = threadIdx.x; i < NL * HD; i += 256) s_emb[i] = emb[i];
    __syncthreads();

    const float4 y = *(const float4*)(Y + (size_t)row * HD + c);
    float s  = y.x + y.y + y.z + y.w;
    float sq = y.x * y.x + y.y * y.y + y.z * y.z + y.w * y.w;
    const float sum   = blk_reduce(s, sbuf);
    const float sumsq = blk_reduce(sq, sbuf);
    const float mu   = sum * (1.0f / HD);
    const float var  = sumsq * (1.0f / HD) - mu * mu;
    const float rstd = rsqrtf(var + 1e-5f);

    const float4 gv = *(const float4*)(g + c);
    const float4 bv = *(const float4*)(bvec + c);
    const float t0 = (y.x - mu) * rstd * gv.x + bv.x;
    const float t1 = (y.y - mu) * rstd * gv.y + bv.y;
    const float t2 = (y.z - mu) * rstd * gv.z + bv.z;
    const float t3 = (y.w - mu) * rstd * gv.w + bv.w;

    float sc[NL];
    #pragma unroll
    for (int n = 0; n < NL; ++n) {
        const float* e = s_emb + n * HD + c;
        float p = t0 * e[0] + t1 * e[1] + t2 * e[2] + t3 * e[3];
        sc[n] = blk_reduce(p, sbuf);
    }

    const float4 mk = *(const float4*)(masks + (size_t)row * 4);
    float wn0 = (mk.x > 0.5f) ? expf(sc[0]) : 0.0f;
    float wn1 = (mk.y > 0.5f) ? expf(sc[1]) : 0.0f;
    float wn2 = (mk.z > 0.5f) ? expf(sc[2]) : 0.0f;
    float wn3 = (mk.w > 0.5f) ? expf(sc[3]) : 0.0f;
    const float tot = wn0 + wn1 + wn2 + wn3;
    const float inv = (tot > 1e-8f) ? (1.0f / tot) : 1.0f;

    const float* e0 = s_emb + 0 * HD + c;
    const float* e1 = s_emb + 1 * HD + c;
    const float* e2 = s_emb + 2 * HD + c;
    const float* e3 = s_emb + 3 * HD + c;
    const float f0 = (wn0 * e0[0] + wn1 * e1[0] + wn2 * e2[0] + wn3 * e3[0]) * inv;
    const float f1 = (wn0 * e0[1] + wn1 * e1[1] + wn2 * e2[1] + wn3 * e3[1]) * inv;
    const float f2 = (wn0 * e0[2] + wn1 * e1[2] + wn2 * e2[2] + wn3 * e3[2]) * inv;
    const float f3 = (wn0 * e0[3] + wn1 * e1[3] + wn2 * e2[3] + wn3 * e3[3]) * inv;

    const float gd = f0 * t0 + f1 * t1 + f2 * t2 + f3 * t3;
    const float gsum = blk_reduce(gd, sbuf);
    const float gate = 1.0f / (1.0f + expf(-gsum * (1.0f / HD)));
    const float og = 1.0f - gate;

    float4 o;
    o.x = gate * f0 + og * t0;
    o.y = gate * f1 + og * t1;
    o.z = gate * f2 + og * t2;
    o.w = gate * f3 + og * t3;
    *(float4*)(Fout + (size_t)row * HD + c) = o;
}

// ---------------------------------------------------------------------------
// Multi-scale windowed means along L (scales 1,3,7,15), fp16 output for GEMM2
// ---------------------------------------------------------------------------
__global__ __launch_bounds__(256) void multiscale_kernel(
    const float* __restrict__ F, __half* __restrict__ A2)
{
    const int L = LSEQ, H = HD;
    const int SL = 128;

    const int gtid = blockIdx.x * 256 + threadIdx.x;
    const int h = gtid & (H - 1);
    const int rest = gtid >> 10;
    const int b = rest & 7;
    const int strip = rest >> 3;
    const int s0 = strip * SL;

    const float* base = F + (size_t)b * L * H + h;
    __half* oA = A2 + (size_t)b * L * H + h;

    const float SW3  = (float)(1.0 / (1.0 + 1.0986122886681098));
    const float SW7  = (float)(1.0 / (1.0 + 1.9459101090932196));
    const float SW15 = (float)(1.0 / (1.0 + 2.7080502011022101));

    if (strip > 0 && strip < 31) {
        float ring[16];
        #pragma unroll
        for (int j = -8; j <= 6; ++j)
            ring[j & 15] = base[(size_t)(s0 + j) * H];

        float s3 = 0.f, s7 = 0.f, s15 = 0.f;
        #pragma unroll
        for (int j = -8; j <= 6; ++j) {
            const float v = ring[j & 15];
            const int d = j + 1;
            if (d >= -7 && d <= 7) s15 += v;
            if (d >= -3 && d <= 3) s7  += v;
            if (d >= -1 && d <= 1) s3  += v;
        }

        const float w3 = SW3 * (1.0f / 3.0f);
        const float w7 = SW7 * (1.0f / 7.0f);
        const float w15 = SW15 * (1.0f / 15.0f);

        #pragma unroll 1
        for (int cch = 0; cch < SL; cch += 16) {
            #pragma unroll
            for (int i = 0; i < 16; ++i) {
                const int l = s0 + cch + i;
                const float nv = base[(size_t)(l + 7) * H];
                ring[(i + 7) & 15] = nv;
                s3  += ring[(i + 1) & 15] - ring[(i - 2) & 15];
                s7  += ring[(i + 3) & 15] - ring[(i - 4) & 15];
                s15 += nv               - ring[(i - 8) & 15];
                const float s1 = ring[i & 15];
                oA[(size_t)l * H] = __float2half_rn(s1 + s3 * w3 + s7 * w7 + s15 * w15);
            }
        }
    } else {
        for (int l = s0; l < s0 + SL; ++l) {
            float s3 = 0.f, s7 = 0.f, s15 = 0.f;
            #pragma unroll
            for (int j = -7; j <= 7; ++j) {
                const int p = l + j;
                const float v = (p >= 0 && p < L) ? base[(size_t)p * H] : 0.0f;
                s15 += v;
                if (j >= -3 && j <= 3) s7 += v;
                if (j >= -1 && j <= 1) s3 += v;
            }
            const float s1 = base[(size_t)l * H];
            const int cnt3  = min(l + 2, L) - max(l - 1, 0);
            const int cnt7  = min(l + 4, L) - max(l - 3, 0);
            const int cnt15 = min(l + 8, L) - max(l - 7, 0);
            const float outv = s1
                + SW3  * s3  / (float)cnt3
                + SW7  * s7  / (float)cnt7
                + SW15 * s15 / (float)cnt15;
            oA[(size_t)l * H] = __float2half_rn(outv);
        }
    }
}

// ---------------------------------------------------------------------------
// LN2 + residual
// ---------------------------------------------------------------------------
__global__ __launch_bounds__(256) void ln2_res_kernel(
    const float* __restrict__ Y, const float* __restrict__ X,
    const float* __restrict__ g, const float* __restrict__ bvec,
    float* __restrict__ out)
{
    __shared__ float sbuf[8];
    const int row = blockIdx.x;
    const int c = threadIdx.x * 4;

    const float4 y = *(const float4*)(Y + (size_t)row * HD + c);
    float s  = y.x + y.y + y.z + y.w;
    float sq = y.x * y.x + y.y * y.y + y.z * y.z + y.w * y.w;
    const float sum   = blk_reduce(s, sbuf);
    const float sumsq = blk_reduce(sq, sbuf);
    const float mu   = sum * (1.0f / HD);
    const float var  = sumsq * (1.0f / HD) - mu * mu;
    const float rstd = rsqrtf(var + 1e-5f);

    const float4 gv = *(const float4*)(g + c);
    const float4 bv = *(const float4*)(bvec + c);
    const float4 xv = *(const float4*)(X + (size_t)row * HD + c);

    float4 o;
    o.x = (y.x - mu) * rstd * gv.x + bv.x + xv.x;
    o.y = (y.y - mu) * rstd * gv.y + bv.y + xv.y;
    o.z = (y.z - mu) * rstd * gv.z + bv.z + xv.z;
    o.w = (y.w - mu) * rstd * gv.w + bv.w + xv.w;
    *(float4*)(out + (size_t)row * HD + c) = o;
}

// ---------------------------------------------------------------------------
// Launcher
// ---------------------------------------------------------------------------
extern "C" void kernel_launch(void* const* d_in, const int* in_sizes, int n_in,
                              void* d_out, int out_size)
{
    const float* X   = (const float*)d_in[0];
    const float* msk = (const float*)d_in[1];
    const float* emb = (const float*)d_in[2];
    const float* ltw = (const float*)d_in[3];
    const float* ltb = (const float*)d_in[4];
    const float* g1  = (const float*)d_in[5];
    const float* b1  = (const float*)d_in[6];
    const float* ftw = (const float*)d_in[7];
    const float* ftb = (const float*)d_in[8];
    const float* g2  = (const float*)d_in[9];
    const float* b2  = (const float*)d_in[10];
    float* out = (float*)d_out;

    float *bufA, *bufB;
    __half *A2, *Wt1, *Wt2;
    cudaGetSymbolAddress((void**)&bufA, g_bufA);
    cudaGetSymbolAddress((void**)&bufB, g_bufB);
    cudaGetSymbolAddress((void**)&A2,  g_A2);
    cudaGetSymbolAddress((void**)&Wt1, g_Wt1);
    cudaGetSymbolAddress((void**)&Wt2, g_Wt2);

    cudaFuncSetAttribute((const void*)gemm_mma_kernel,
                         cudaFuncAttributeMaxDynamicSharedMemorySize, GEMM_SMEM);

    const dim3 ggrid(HD / BN, MROWS / BM);   // (4, 256)

    // weight transposes to fp16 (every call; deterministic)
    convW_kernel<<<(HD * HD) / 256, 256>>>(ltw, Wt1);
    convW_kernel<<<(HD * HD) / 256, 256>>>(ftw, Wt2);

    // 1) Y1 = X @ lt_w + lt_b
    convA_kernel<<<(MROWS * HD / 4) / 256, 256>>>(X, A2);
    gemm_mma_kernel<<<ggrid, 256, GEMM_SMEM>>>(A2, Wt1, ltb, bufA);
    // 2) F = fusion(LN1(Y1))
    ln1_fusion_kernel<<<MROWS, 256>>>(bufA, msk, emb, g1, b1, bufB);
    // 3) agg = multiscale(F), fp16 out -> A2
    multiscale_kernel<<<(BDIM * HD * 32) / 256, 256>>>(bufB, A2);
    // 4) Y2 = agg @ ft_w + ft_b
    gemm_mma_kernel<<<ggrid, 256, GEMM_SMEM>>>(A2, Wt2, ftb, bufA);
    // 5) out = LN2(Y2) + X
    ln2_res_kernel<<<MROWS, 256>>>(bufA, X, g2, b2, out);
}